// round 11
// baseline (speedup 1.0000x reference)
#include <cuda_runtime.h>
#include <cuda_bf16.h>
#include <cstdint>

// ---------------- problem constants ----------------
#define Bq     256
#define Tq     16
#define Cq     40
#define Hq     4
#define Dq     10
#define Vq     50257
#define BT     (Bq*Tq)          // 4096
#define VP2    50688            // padded vocab
#define KK     128              // split-K: [xh(40) xl(40) xh(40) 0(8)]
#define CTILE  128              // cols per CTA
#define NCT    393              // ceil(Vq/128)
#define NRT    32               // BT/128
#define NTILES 786              // sum-exp partials per row (64 cols each)
#define THR    256

// ---------------- device scratch ----------------
__device__ float           g_out[BT * Cq];
__device__ __nv_bfloat16   g_Axs[BT * KK];          // A[m][k]
__device__ __nv_bfloat16   g_Wt[(size_t)VP2 * KK];  // B[n][k]
__device__ float           g_psum[(size_t)BT * NTILES];
__device__ float           g_tgt[BT];
__device__ float           g_part[512];

// ---------------- SMEM layout (bytes) ----------------
#define STRB     272            // padded A/B row stride in bytes (136 bf16)
#define OFF_BIAS 0              // 128 floats
#define OFF_TGT  512            // 128 ints
#define OFF_A    1024           // 128 x 272
#define OFF_B    35840          // 128 x 272
#define SMEM_SZ  70656
#define CSTR     132            // C staging stride in words (reuses OFF_A region)

// ---------------- PTX helpers ----------------
__device__ __forceinline__ uint32_t smem_u32(const void* p) {
    uint32_t a;
    asm("{ .reg .u64 t; cvta.to.shared.u64 t, %1; cvt.u32.u64 %0, t; }" : "=r"(a) : "l"(p));
    return a;
}
__device__ __forceinline__ void cp16(uint32_t dst, const void* src) {
    asm volatile("cp.async.cg.shared.global [%0], [%1], 16;" :: "r"(dst), "l"(src));
}
__device__ __forceinline__ void cp_commit_wait() {
    asm volatile("cp.async.commit_group;");
    asm volatile("cp.async.wait_group 0;" ::: "memory");
}
__device__ __forceinline__ void ldm_x4(uint32_t& r0, uint32_t& r1, uint32_t& r2, uint32_t& r3,
                                       uint32_t addr) {
    asm volatile("ldmatrix.sync.aligned.m8n8.x4.shared.b16 {%0,%1,%2,%3}, [%4];"
                 : "=r"(r0), "=r"(r1), "=r"(r2), "=r"(r3) : "r"(addr));
}
__device__ __forceinline__ void mma16816(float* c, const uint32_t* a, const uint32_t* b) {
    asm volatile(
        "mma.sync.aligned.m16n8k16.row.col.f32.bf16.bf16.f32 "
        "{%0,%1,%2,%3}, {%4,%5,%6,%7}, {%8,%9}, {%0,%1,%2,%3};"
        : "+f"(c[0]), "+f"(c[1]), "+f"(c[2]), "+f"(c[3])
        : "r"(a[0]), "r"(a[1]), "r"(a[2]), "r"(a[3]), "r"(b[0]), "r"(b[1]));
}

// ---------------- kernel: split lm_W -> g_Wt (B[n][k]) ----------------
__global__ __launch_bounds__(256)
void wprep_kernel(const float* __restrict__ lm_W) {
    int n = blockIdx.x * 256 + threadIdx.x;
    if (n >= VP2) return;
    bool valid = n < Vq;
    __nv_bfloat16 vals[KK];
    #pragma unroll
    for (int k = 0; k < 40; k++) {
        float w = valid ? lm_W[(size_t)k * Vq + n] : 0.f;
        __nv_bfloat16 h = __float2bfloat16(w);
        __nv_bfloat16 l = __float2bfloat16(w - __bfloat162float(h));
        vals[k]      = h;   // pairs with xh
        vals[40 + k] = h;   // pairs with xl
        vals[80 + k] = l;   // pairs with xh
    }
    #pragma unroll
    for (int k = 120; k < 128; k++) vals[k] = __float2bfloat16(0.f);
    const uint4* vp = reinterpret_cast<const uint4*>(vals);
    uint4* dst = reinterpret_cast<uint4*>(&g_Wt[(size_t)n * KK]);
    #pragma unroll
    for (int i = 0; i < 16; i++) dst[i] = vp[i];
}

// ---------------- kernel: embed + attention (one CTA per batch) ----------------
__global__ __launch_bounds__(128)
void attn_kernel(const int* __restrict__ idx,
                 const float* __restrict__ tok_emb,
                 const float* __restrict__ pos_emb,
                 const float* __restrict__ Wqp,
                 const float* __restrict__ Wkp,
                 const float* __restrict__ Wvp) {
    __shared__ float xs[Tq][Cq];
    __shared__ float qs[Hq][Tq][Dq];
    __shared__ float ks[Hq][Tq][Dq];
    __shared__ float vs[Hq][Tq][Dq];
    __shared__ float at[Hq][Tq][Tq];

    int b = blockIdx.x, tid = threadIdx.x;
    for (int i = tid; i < Tq * Cq; i += 128) {
        int t = i / Cq, c = i - t * Cq;
        int tok = idx[b * Tq + t];
        xs[t][c] = tok_emb[(size_t)tok * Cq + c] + pos_emb[t * Cq + c];
    }
    __syncthreads();

    int h = tid >> 5, lane = tid & 31;
    for (int i = lane; i < Tq * Dq; i += 32) {
        int t = i / Dq, d = i - t * Dq;
        float aq = 0.f, ak = 0.f, av = 0.f;
        #pragma unroll
        for (int c = 0; c < Cq; c++) {
            float x = xs[t][c];
            aq = fmaf(x, Wqp[(h * Cq + c) * Dq + d], aq);
            ak = fmaf(x, Wkp[(h * Cq + c) * Dq + d], ak);
            av = fmaf(x, Wvp[(h * Cq + c) * Dq + d], av);
        }
        qs[h][t][d] = aq; ks[h][t][d] = ak; vs[h][t][d] = av;
    }
    __syncwarp();
    for (int i = lane; i < Tq * Tq; i += 32) {
        int t = i / Tq, s = i - t * Tq;
        float a;
        if (s <= t) {
            a = 0.f;
            #pragma unroll
            for (int d = 0; d < Dq; d++) a = fmaf(qs[h][t][d], ks[h][s][d], a);
        } else a = -INFINITY;
        at[h][t][s] = a;
    }
    __syncwarp();
    if (lane < Tq) {
        int t = lane;
        float m = -INFINITY;
        for (int s = 0; s <= t; s++) m = fmaxf(m, at[h][t][s]);
        float sum = 0.f;
        for (int s = 0; s <= t; s++) { float e = expf(at[h][t][s] - m); at[h][t][s] = e; sum += e; }
        float inv = 1.f / sum;
        for (int s = 0; s <= t; s++) at[h][t][s] *= inv;
    }
    __syncwarp();
    for (int i = lane; i < Tq * Dq; i += 32) {
        int t = i / Dq, d = i - t * Dq;
        float a = 0.f;
        for (int s = 0; s <= t; s++) a = fmaf(at[h][t][s], vs[h][s][d], a);
        g_out[((size_t)(b * Tq + t)) * Cq + h * Dq + d] = a;
    }
}

// ---------------- kernel: split attention output rows -> g_Axs ----------------
__global__ __launch_bounds__(256)
void asplit_kernel() {
    int row = blockIdx.x * 256 + threadIdx.x;
    __nv_bfloat16 vals[KK];
    #pragma unroll
    for (int k = 0; k < 40; k++) {
        float x = g_out[(size_t)row * Cq + k];
        __nv_bfloat16 h = __float2bfloat16(x);
        __nv_bfloat16 l = __float2bfloat16(x - __bfloat162float(h));
        vals[k]      = h;
        vals[40 + k] = l;
        vals[80 + k] = h;
    }
    #pragma unroll
    for (int k = 120; k < 128; k++) vals[k] = __float2bfloat16(0.f);
    const uint4* vp = reinterpret_cast<const uint4*>(vals);
    uint4* dst = reinterpret_cast<uint4*>(&g_Axs[(size_t)row * KK]);
    #pragma unroll
    for (int i = 0; i < 16; i++) dst[i] = vp[i];
}

// ---------------- main: HMMA GEMM 128x128 + staged coalesced writeback, 3 CTA/SM ----
__global__ __launch_bounds__(THR, 3)
void mma_kernel(const float* __restrict__ lm_b,
                const int* __restrict__ targets,
                float* __restrict__ logits,
                int write_logits) {
    extern __shared__ char smem[];
    int tid = threadIdx.x, wid = tid >> 5, lane = tid & 31;
    int ctile = blockIdx.x, rtile = blockIdx.y;
    int c0 = ctile * CTILE, r0 = rtile * 128;

    float* s_bias = reinterpret_cast<float*>(smem + OFF_BIAS);
    int*   s_tgt  = reinterpret_cast<int*>(smem + OFF_TGT);
    uint32_t sbase = smem_u32(smem);

    if (tid < 128) {
        int c = c0 + tid;
        s_bias[tid] = (c < Vq) ? lm_b[c] : 0.f;
        s_tgt[tid]  = targets[r0 + tid];
    }

    // async-load A tile 128 x 128 bf16 (padded stride)
    #pragma unroll
    for (int it = 0; it < 8; it++) {
        int i = tid + it * THR;
        int m = i >> 4, k16 = i & 15;
        cp16(sbase + OFF_A + m * STRB + k16 * 16,
             &g_Axs[(size_t)(r0 + m) * KK + k16 * 8]);
    }
    // async-load B tile 128 x 128 bf16
    #pragma unroll
    for (int it = 0; it < 8; it++) {
        int i = tid + it * THR;
        int n = i >> 4, k16 = i & 15;
        cp16(sbase + OFF_B + n * STRB + k16 * 16,
             &g_Wt[(size_t)(c0 + n) * KK + k16 * 8]);
    }
    cp_commit_wait();
    __syncthreads();

    // warp tiling: rows (wid&3)*32, cols (wid>>2)*64
    int mrow0 = (wid & 3) * 32;
    int ncol0 = (wid >> 2) * 64;
    int g = lane >> 2, t = lane & 3;

    uint32_t a_addr0 = sbase + OFF_A + (mrow0 + (lane & 15)) * STRB + (lane >> 4) * 16;
    uint32_t a_addr1 = a_addr0 + 16 * STRB;
    uint32_t b_addr0 = sbase + OFF_B + (ncol0 + ((lane >> 4) << 3) + (lane & 7)) * STRB + ((lane >> 3) & 1) * 16;
    uint32_t b_addr1 = b_addr0 + 16 * STRB;
    uint32_t b_addr2 = b_addr1 + 16 * STRB;
    uint32_t b_addr3 = b_addr2 + 16 * STRB;

    float acc[2][8][4];
    #pragma unroll
    for (int mt = 0; mt < 2; mt++)
        #pragma unroll
        for (int nt = 0; nt < 8; nt++)
            #pragma unroll
            for (int j = 0; j < 4; j++) acc[mt][nt][j] = 0.f;

    #pragma unroll
    for (int ks = 0; ks < 8; ks++) {
        uint32_t ka = ks * 32;
        uint32_t af[2][4];
        ldm_x4(af[0][0], af[0][1], af[0][2], af[0][3], a_addr0 + ka);
        ldm_x4(af[1][0], af[1][1], af[1][2], af[1][3], a_addr1 + ka);
        uint32_t bf[8][2];
        ldm_x4(bf[0][0], bf[0][1], bf[1][0], bf[1][1], b_addr0 + ka);
        ldm_x4(bf[2][0], bf[2][1], bf[3][0], bf[3][1], b_addr1 + ka);
        ldm_x4(bf[4][0], bf[4][1], bf[5][0], bf[5][1], b_addr2 + ka);
        ldm_x4(bf[6][0], bf[6][1], bf[7][0], bf[7][1], b_addr3 + ka);
        #pragma unroll
        for (int nt = 0; nt < 8; nt++) {
            mma16816(acc[0][nt], af[0], bf[nt]);
            mma16816(acc[1][nt], af[1], bf[nt]);
        }
    }

    __syncthreads();   // A/B smem dead; reuse as C staging

    // -------- phase 1: bias + sum-exp from registers (no max pass),
    //          stage biased logits to smem (float2) --------
    float* Cs = reinterpret_cast<float*>(smem + OFF_A);
    int half = wid >> 2;
    int tix = ctile * 2 + half;
    bool fullcols = (c0 + CTILE) <= Vq;

    float2 bs[8];
    #pragma unroll
    for (int nt = 0; nt < 8; nt++)
        bs[nt] = *reinterpret_cast<const float2*>(&s_bias[ncol0 + nt * 8 + 2 * t]);

    #pragma unroll
    for (int mt = 0; mt < 2; mt++) {
        #pragma unroll
        for (int rh = 0; rh < 2; rh++) {
            int rl = mrow0 + mt * 16 + rh * 8 + g;
            int grow = r0 + rl;
            float s = 0.f;
            #pragma unroll
            for (int nt = 0; nt < 8; nt++) {
                float v0 = acc[mt][nt][rh * 2 + 0] + bs[nt].x;
                float v1 = acc[mt][nt][rh * 2 + 1] + bs[nt].y;
                float2 p; p.x = v0; p.y = v1;
                *reinterpret_cast<float2*>(&Cs[rl * CSTR + ncol0 + nt * 8 + 2 * t]) = p;
                if (fullcols) {
                    s += __expf(v0) + __expf(v1);
                } else {
                    int col = c0 + ncol0 + nt * 8 + 2 * t;
                    if (col < Vq)     s += __expf(v0);
                    if (col + 1 < Vq) s += __expf(v1);
                }
            }
            s += __shfl_xor_sync(0xffffffffu, s, 1);
            s += __shfl_xor_sync(0xffffffffu, s, 2);
            if (t == 0) g_psum[(size_t)grow * NTILES + tix] = s;
        }
    }
    __syncthreads();

    // -------- phase 2: truly coalesced writeback (lane-contiguous STG.32) --------
    if (write_logits) {
        if (fullcols) {
            #pragma unroll
            for (int i = 0; i < 16; i++) {
                int rl = wid * 16 + i;
                size_t rowbase = (size_t)(r0 + rl) * (size_t)Vq + c0;
                float v0 = Cs[rl * CSTR + lane];
                float v1 = Cs[rl * CSTR + lane + 32];
                float v2 = Cs[rl * CSTR + lane + 64];
                float v3 = Cs[rl * CSTR + lane + 96];
                __stcs(&logits[rowbase + lane],      v0);
                __stcs(&logits[rowbase + lane + 32], v1);
                __stcs(&logits[rowbase + lane + 64], v2);
                __stcs(&logits[rowbase + lane + 96], v3);
            }
        } else {
            for (int i = 0; i < 16; i++) {
                int rl = wid * 16 + i;
                size_t rowbase = (size_t)(r0 + rl) * (size_t)Vq;
                #pragma unroll
                for (int j = 0; j < 4; j++) {
                    int col = c0 + lane + 32 * j;
                    if (col < Vq)
                        __stcs(&logits[rowbase + col], Cs[rl * CSTR + lane + 32 * j]);
                }
            }
        }
    } else {
        // no logits output: gather target logit from smem directly
        if (tid < 128) {
            int tg = s_tgt[tid];
            if (tg >= c0 && tg < c0 + CTILE)
                g_tgt[r0 + tid] = Cs[tid * CSTR + (tg - c0)];
        }
    }
}

// ---------------- target gather (after logits written) ----------------
__global__ void tgt_kernel(const int* __restrict__ targets,
                           const float* __restrict__ logits, int enable) {
    if (!enable) return;
    int row = blockIdx.x * 256 + threadIdx.x;
    g_tgt[row] = logits[(size_t)row * Vq + targets[row]];
}

// ---------------- rowloss: warp per row over 786 sum partials ----------------
__global__ __launch_bounds__(256)
void rowloss_kernel() {
    int wid = threadIdx.x >> 5, lane = threadIdx.x & 31;
    int row = blockIdx.x * 8 + wid;   // grid 512
    const float* ps = &g_psum[(size_t)row * NTILES];
    float s = 0.f;
    for (int t = lane; t < NTILES; t += 32) s += ps[t];
    #pragma unroll
    for (int o = 16; o >= 1; o >>= 1) s += __shfl_xor_sync(0xffffffffu, s, o);
    __shared__ float sl[8];
    if (lane == 0) sl[wid] = logf(s) - g_tgt[row];
    __syncthreads();
    if (threadIdx.x == 0) {
        float tt = 0.f;
        #pragma unroll
        for (int w = 0; w < 8; w++) tt += sl[w];
        g_part[blockIdx.x] = tt;
    }
}

__global__ void final_kernel(float* __restrict__ out, int loss_idx, int do_loss) {
    if (!do_loss) return;
    __shared__ float sb[512];
    sb[threadIdx.x] = g_part[threadIdx.x];
    __syncthreads();
    for (int o = 256; o >= 1; o >>= 1) {
        if (threadIdx.x < o) sb[threadIdx.x] += sb[threadIdx.x + o];
        __syncthreads();
    }
    if (threadIdx.x == 0) out[loss_idx] = sb[0] * (1.0f / (float)BT);
}

// ---------------- launch ----------------
extern "C" void kernel_launch(void* const* d_in, const int* in_sizes, int n_in,
                              void* d_out, int out_size) {
    const int*   idx     = (const int*)d_in[0];
    const int*   targets = (const int*)d_in[1];
    const float* tok_emb = (const float*)d_in[2];
    const float* pos_emb = (const float*)d_in[3];
    const float* Wqp     = (const float*)d_in[4];
    const float* Wkp     = (const float*)d_in[5];
    const float* Wvp     = (const float*)d_in[6];
    const float* lm_W    = (const float*)d_in[7];
    const float* lm_b    = (const float*)d_in[8];
    float* out = (float*)d_out;

    const long long LOGITS = (long long)BT * Vq;
    int write_logits = (out_size >= LOGITS) ? 1 : 0;
    int do_loss = 1;
    int loss_idx;
    if (write_logits) {
        if ((long long)out_size > LOGITS) loss_idx = (int)LOGITS;
        else { do_loss = 0; loss_idx = 0; }
    } else {
        loss_idx = out_size - 1;
    }

    cudaFuncSetAttribute(mma_kernel, cudaFuncAttributeMaxDynamicSharedMemorySize, SMEM_SZ);

    wprep_kernel<<<(VP2 + 255) / 256, 256>>>(lm_W);
    attn_kernel<<<Bq, 128>>>(idx, tok_emb, pos_emb, Wqp, Wkp, Wvp);
    asplit_kernel<<<BT / 256, 256>>>();
    mma_kernel<<<dim3(NCT, NRT), THR, SMEM_SZ>>>(lm_b, targets, out, write_logits);
    tgt_kernel<<<BT / 256, 256>>>(targets, out, write_logits);
    rowloss_kernel<<<512, 256>>>();
    final_kernel<<<1, 512>>>(out, loss_idx, do_loss);
}

// round 12
// speedup vs baseline: 1.2462x; 1.2462x over previous
#include <cuda_runtime.h>
#include <cuda_bf16.h>
#include <cstdint>

// ---------------- problem constants ----------------
#define Bq     256
#define Tq     16
#define Cq     40
#define Hq     4
#define Dq     10
#define Vq     50257
#define BT     (Bq*Tq)          // 4096
#define VP2    50688            // padded vocab
#define KK     128              // split-K: [xh(40) xl(40) xh(40) 0(8)]
#define CTILE  128              // cols per CTA
#define NCT    393              // ceil(Vq/128)
#define NRT    32               // BT/128
#define NTILES 786              // sum-exp partials per row (64 cols each)
#define THR    256

// ---------------- device scratch ----------------
__device__ float           g_out[BT * Cq];
__device__ __nv_bfloat16   g_Axs[BT * KK];          // A[m][k]
__device__ __nv_bfloat16   g_Wt[(size_t)VP2 * KK];  // B[n][k]
__device__ float           g_psum[(size_t)BT * NTILES];
__device__ float           g_tgt[BT];
__device__ float           g_part[512];

// ---------------- SMEM layout (bytes) ----------------
#define STRB     272            // padded A/B row stride in bytes (136 bf16)
#define OFF_BIAS 0              // 128 floats
#define OFF_TGT  512            // 128 ints
#define OFF_A    1024           // 128 x 272
#define OFF_B    35840          // 128 x 272
#define SMEM_SZ  70656
#define CSTR     132            // C staging stride in words (reuses OFF_A region)

// ---------------- PTX helpers ----------------
__device__ __forceinline__ uint32_t smem_u32(const void* p) {
    uint32_t a;
    asm("{ .reg .u64 t; cvta.to.shared.u64 t, %1; cvt.u32.u64 %0, t; }" : "=r"(a) : "l"(p));
    return a;
}
__device__ __forceinline__ void cp16(uint32_t dst, const void* src) {
    asm volatile("cp.async.cg.shared.global [%0], [%1], 16;" :: "r"(dst), "l"(src));
}
__device__ __forceinline__ void cp_commit_wait() {
    asm volatile("cp.async.commit_group;");
    asm volatile("cp.async.wait_group 0;" ::: "memory");
}
__device__ __forceinline__ void ldm_x4(uint32_t& r0, uint32_t& r1, uint32_t& r2, uint32_t& r3,
                                       uint32_t addr) {
    asm volatile("ldmatrix.sync.aligned.m8n8.x4.shared.b16 {%0,%1,%2,%3}, [%4];"
                 : "=r"(r0), "=r"(r1), "=r"(r2), "=r"(r3) : "r"(addr));
}
__device__ __forceinline__ void mma16816(float* c, const uint32_t* a, const uint32_t* b) {
    asm volatile(
        "mma.sync.aligned.m16n8k16.row.col.f32.bf16.bf16.f32 "
        "{%0,%1,%2,%3}, {%4,%5,%6,%7}, {%8,%9}, {%0,%1,%2,%3};"
        : "+f"(c[0]), "+f"(c[1]), "+f"(c[2]), "+f"(c[3])
        : "r"(a[0]), "r"(a[1]), "r"(a[2]), "r"(a[3]), "r"(b[0]), "r"(b[1]));
}

// ---------------- kernel: split lm_W -> g_Wt (B[n][k]) ----------------
__global__ __launch_bounds__(256)
void wprep_kernel(const float* __restrict__ lm_W) {
    int n = blockIdx.x * 256 + threadIdx.x;
    if (n >= VP2) return;
    bool valid = n < Vq;
    __nv_bfloat16 vals[KK];
    #pragma unroll
    for (int k = 0; k < 40; k++) {
        float w = valid ? lm_W[(size_t)k * Vq + n] : 0.f;
        __nv_bfloat16 h = __float2bfloat16(w);
        __nv_bfloat16 l = __float2bfloat16(w - __bfloat162float(h));
        vals[k]      = h;   // pairs with xh
        vals[40 + k] = h;   // pairs with xl
        vals[80 + k] = l;   // pairs with xh
    }
    #pragma unroll
    for (int k = 120; k < 128; k++) vals[k] = __float2bfloat16(0.f);
    const uint4* vp = reinterpret_cast<const uint4*>(vals);
    uint4* dst = reinterpret_cast<uint4*>(&g_Wt[(size_t)n * KK]);
    #pragma unroll
    for (int i = 0; i < 16; i++) dst[i] = vp[i];
}

// ---------------- kernel: embed + attention (one CTA per batch) ----------------
__global__ __launch_bounds__(128)
void attn_kernel(const int* __restrict__ idx,
                 const float* __restrict__ tok_emb,
                 const float* __restrict__ pos_emb,
                 const float* __restrict__ Wqp,
                 const float* __restrict__ Wkp,
                 const float* __restrict__ Wvp) {
    __shared__ float xs[Tq][Cq];
    __shared__ float qs[Hq][Tq][Dq];
    __shared__ float ks[Hq][Tq][Dq];
    __shared__ float vs[Hq][Tq][Dq];
    __shared__ float at[Hq][Tq][Tq];

    int b = blockIdx.x, tid = threadIdx.x;
    for (int i = tid; i < Tq * Cq; i += 128) {
        int t = i / Cq, c = i - t * Cq;
        int tok = idx[b * Tq + t];
        xs[t][c] = tok_emb[(size_t)tok * Cq + c] + pos_emb[t * Cq + c];
    }
    __syncthreads();

    int h = tid >> 5, lane = tid & 31;
    for (int i = lane; i < Tq * Dq; i += 32) {
        int t = i / Dq, d = i - t * Dq;
        float aq = 0.f, ak = 0.f, av = 0.f;
        #pragma unroll
        for (int c = 0; c < Cq; c++) {
            float x = xs[t][c];
            aq = fmaf(x, Wqp[(h * Cq + c) * Dq + d], aq);
            ak = fmaf(x, Wkp[(h * Cq + c) * Dq + d], ak);
            av = fmaf(x, Wvp[(h * Cq + c) * Dq + d], av);
        }
        qs[h][t][d] = aq; ks[h][t][d] = ak; vs[h][t][d] = av;
    }
    __syncwarp();
    for (int i = lane; i < Tq * Tq; i += 32) {
        int t = i / Tq, s = i - t * Tq;
        float a;
        if (s <= t) {
            a = 0.f;
            #pragma unroll
            for (int d = 0; d < Dq; d++) a = fmaf(qs[h][t][d], ks[h][s][d], a);
        } else a = -INFINITY;
        at[h][t][s] = a;
    }
    __syncwarp();
    if (lane < Tq) {
        int t = lane;
        float m = -INFINITY;
        for (int s = 0; s <= t; s++) m = fmaxf(m, at[h][t][s]);
        float sum = 0.f;
        for (int s = 0; s <= t; s++) { float e = expf(at[h][t][s] - m); at[h][t][s] = e; sum += e; }
        float inv = 1.f / sum;
        for (int s = 0; s <= t; s++) at[h][t][s] *= inv;
    }
    __syncwarp();
    for (int i = lane; i < Tq * Dq; i += 32) {
        int t = i / Dq, d = i - t * Dq;
        float a = 0.f;
        for (int s = 0; s <= t; s++) a = fmaf(at[h][t][s], vs[h][s][d], a);
        g_out[((size_t)(b * Tq + t)) * Cq + h * Dq + d] = a;
    }
}

// ---------------- kernel: split attention output rows -> g_Axs ----------------
__global__ __launch_bounds__(256)
void asplit_kernel() {
    int row = blockIdx.x * 256 + threadIdx.x;
    __nv_bfloat16 vals[KK];
    #pragma unroll
    for (int k = 0; k < 40; k++) {
        float x = g_out[(size_t)row * Cq + k];
        __nv_bfloat16 h = __float2bfloat16(x);
        __nv_bfloat16 l = __float2bfloat16(x - __bfloat162float(h));
        vals[k]      = h;
        vals[40 + k] = l;
        vals[80 + k] = h;
    }
    #pragma unroll
    for (int k = 120; k < 128; k++) vals[k] = __float2bfloat16(0.f);
    const uint4* vp = reinterpret_cast<const uint4*>(vals);
    uint4* dst = reinterpret_cast<uint4*>(&g_Axs[(size_t)row * KK]);
    #pragma unroll
    for (int i = 0; i < 16; i++) dst[i] = vp[i];
}

// ---------------- main: HMMA GEMM 128x128 + warp-local staged writeback ----------------
__global__ __launch_bounds__(THR)
void mma_kernel(const float* __restrict__ lm_b,
                const int* __restrict__ targets,
                float* __restrict__ logits,
                int write_logits) {
    extern __shared__ char smem[];
    int tid = threadIdx.x, wid = tid >> 5, lane = tid & 31;
    int ctile = blockIdx.x, rtile = blockIdx.y;
    int c0 = ctile * CTILE, r0 = rtile * 128;

    float* s_bias = reinterpret_cast<float*>(smem + OFF_BIAS);
    int*   s_tgt  = reinterpret_cast<int*>(smem + OFF_TGT);
    uint32_t sbase = smem_u32(smem);

    if (tid < 128) {
        int c = c0 + tid;
        s_bias[tid] = (c < Vq) ? lm_b[c] : 0.f;
        s_tgt[tid]  = targets[r0 + tid];
    }

    // async-load A tile 128 x 128 bf16 (padded stride)
    #pragma unroll
    for (int it = 0; it < 8; it++) {
        int i = tid + it * THR;
        int m = i >> 4, k16 = i & 15;
        cp16(sbase + OFF_A + m * STRB + k16 * 16,
             &g_Axs[(size_t)(r0 + m) * KK + k16 * 8]);
    }
    // async-load B tile 128 x 128 bf16
    #pragma unroll
    for (int it = 0; it < 8; it++) {
        int i = tid + it * THR;
        int n = i >> 4, k16 = i & 15;
        cp16(sbase + OFF_B + n * STRB + k16 * 16,
             &g_Wt[(size_t)(c0 + n) * KK + k16 * 8]);
    }
    cp_commit_wait();
    __syncthreads();

    // warp tiling: rows (wid&3)*32, cols (wid>>2)*64
    int mrow0 = (wid & 3) * 32;
    int ncol0 = (wid >> 2) * 64;
    int g = lane >> 2, t = lane & 3;

    uint32_t a_addr0 = sbase + OFF_A + (mrow0 + (lane & 15)) * STRB + (lane >> 4) * 16;
    uint32_t a_addr1 = a_addr0 + 16 * STRB;
    uint32_t b_addr0 = sbase + OFF_B + (ncol0 + ((lane >> 4) << 3) + (lane & 7)) * STRB + ((lane >> 3) & 1) * 16;
    uint32_t b_addr1 = b_addr0 + 16 * STRB;
    uint32_t b_addr2 = b_addr1 + 16 * STRB;
    uint32_t b_addr3 = b_addr2 + 16 * STRB;

    float acc[2][8][4];
    #pragma unroll
    for (int mt = 0; mt < 2; mt++)
        #pragma unroll
        for (int nt = 0; nt < 8; nt++)
            #pragma unroll
            for (int j = 0; j < 4; j++) acc[mt][nt][j] = 0.f;

    #pragma unroll
    for (int ks = 0; ks < 8; ks++) {
        uint32_t ka = ks * 32;
        uint32_t af[2][4];
        ldm_x4(af[0][0], af[0][1], af[0][2], af[0][3], a_addr0 + ka);
        ldm_x4(af[1][0], af[1][1], af[1][2], af[1][3], a_addr1 + ka);
        uint32_t bf[8][2];
        ldm_x4(bf[0][0], bf[0][1], bf[1][0], bf[1][1], b_addr0 + ka);
        ldm_x4(bf[2][0], bf[2][1], bf[3][0], bf[3][1], b_addr1 + ka);
        ldm_x4(bf[4][0], bf[4][1], bf[5][0], bf[5][1], b_addr2 + ka);
        ldm_x4(bf[6][0], bf[6][1], bf[7][0], bf[7][1], b_addr3 + ka);
        #pragma unroll
        for (int nt = 0; nt < 8; nt++) {
            mma16816(acc[0][nt], af[0], bf[nt]);
            mma16816(acc[1][nt], af[1], bf[nt]);
        }
    }

    __syncthreads();   // all warps done reading A/B smem; reuse as C staging

    // -------- phase 1: bias + sum-exp from registers (no max pass),
    //          stage biased logits to this warp's own smem block --------
    float* Cs = reinterpret_cast<float*>(smem + OFF_A);
    int half = wid >> 2;
    int tix = ctile * 2 + half;
    bool fullcols = (c0 + CTILE) <= Vq;

    float2 bs[8];
    #pragma unroll
    for (int nt = 0; nt < 8; nt++)
        bs[nt] = *reinterpret_cast<const float2*>(&s_bias[ncol0 + nt * 8 + 2 * t]);

    #pragma unroll
    for (int mt = 0; mt < 2; mt++) {
        #pragma unroll
        for (int rh = 0; rh < 2; rh++) {
            int rl = mrow0 + mt * 16 + rh * 8 + g;
            int grow = r0 + rl;
            float s = 0.f;
            #pragma unroll
            for (int nt = 0; nt < 8; nt++) {
                float v0 = acc[mt][nt][rh * 2 + 0] + bs[nt].x;
                float v1 = acc[mt][nt][rh * 2 + 1] + bs[nt].y;
                float2 p; p.x = v0; p.y = v1;
                *reinterpret_cast<float2*>(&Cs[rl * CSTR + ncol0 + nt * 8 + 2 * t]) = p;
                if (fullcols) {
                    s += __expf(v0) + __expf(v1);
                } else {
                    int col = c0 + ncol0 + nt * 8 + 2 * t;
                    if (col < Vq)     s += __expf(v0);
                    if (col + 1 < Vq) s += __expf(v1);
                }
            }
            s += __shfl_xor_sync(0xffffffffu, s, 1);
            s += __shfl_xor_sync(0xffffffffu, s, 2);
            if (t == 0) g_psum[(size_t)grow * NTILES + tix] = s;
        }
    }
    __syncwarp();      // warp-local staging visible to all lanes of this warp

    // -------- phase 2: warp-local coalesced writeback (own 32 rows x 64 cols) --------
    if (write_logits) {
        if (fullcols) {
            #pragma unroll
            for (int i = 0; i < 32; i++) {
                int rl = mrow0 + i;
                size_t rowbase = (size_t)(r0 + rl) * (size_t)Vq + c0 + ncol0;
                float v0 = Cs[rl * CSTR + ncol0 + lane];
                float v1 = Cs[rl * CSTR + ncol0 + lane + 32];
                __stcs(&logits[rowbase + lane],      v0);
                __stcs(&logits[rowbase + lane + 32], v1);
            }
        } else {
            for (int i = 0; i < 32; i++) {
                int rl = mrow0 + i;
                size_t rowbase = (size_t)(r0 + rl) * (size_t)Vq;
                int col0w = c0 + ncol0 + lane;
                if (col0w < Vq)
                    __stcs(&logits[rowbase + col0w], Cs[rl * CSTR + ncol0 + lane]);
                if (col0w + 32 < Vq)
                    __stcs(&logits[rowbase + col0w + 32], Cs[rl * CSTR + ncol0 + lane + 32]);
            }
        }
    } else {
        // no logits output: gather target logit from this warp's staged block
        int rl = mrow0 + lane;                 // 32 rows per warp, one per lane
        int tg = s_tgt[rl];
        int lo = c0 + ncol0;
        if (tg >= lo && tg < lo + 64)
            g_tgt[r0 + rl] = Cs[rl * CSTR + (tg - c0)];
    }
}

// ---------------- target gather (after logits written) ----------------
__global__ void tgt_kernel(const int* __restrict__ targets,
                           const float* __restrict__ logits, int enable) {
    if (!enable) return;
    int row = blockIdx.x * 256 + threadIdx.x;
    g_tgt[row] = logits[(size_t)row * Vq + targets[row]];
}

// ---------------- rowloss: warp per row over 786 sum partials ----------------
__global__ __launch_bounds__(256)
void rowloss_kernel() {
    int wid = threadIdx.x >> 5, lane = threadIdx.x & 31;
    int row = blockIdx.x * 8 + wid;   // grid 512
    const float* ps = &g_psum[(size_t)row * NTILES];
    float s = 0.f;
    for (int t = lane; t < NTILES; t += 32) s += ps[t];
    #pragma unroll
    for (int o = 16; o >= 1; o >>= 1) s += __shfl_xor_sync(0xffffffffu, s, o);
    __shared__ float sl[8];
    if (lane == 0) sl[wid] = logf(s) - g_tgt[row];
    __syncthreads();
    if (threadIdx.x == 0) {
        float tt = 0.f;
        #pragma unroll
        for (int w = 0; w < 8; w++) tt += sl[w];
        g_part[blockIdx.x] = tt;
    }
}

__global__ void final_kernel(float* __restrict__ out, int loss_idx, int do_loss) {
    if (!do_loss) return;
    __shared__ float sb[512];
    sb[threadIdx.x] = g_part[threadIdx.x];
    __syncthreads();
    for (int o = 256; o >= 1; o >>= 1) {
        if (threadIdx.x < o) sb[threadIdx.x] += sb[threadIdx.x + o];
        __syncthreads();
    }
    if (threadIdx.x == 0) out[loss_idx] = sb[0] * (1.0f / (float)BT);
}

// ---------------- launch ----------------
extern "C" void kernel_launch(void* const* d_in, const int* in_sizes, int n_in,
                              void* d_out, int out_size) {
    const int*   idx     = (const int*)d_in[0];
    const int*   targets = (const int*)d_in[1];
    const float* tok_emb = (const float*)d_in[2];
    const float* pos_emb = (const float*)d_in[3];
    const float* Wqp     = (const float*)d_in[4];
    const float* Wkp     = (const float*)d_in[5];
    const float* Wvp     = (const float*)d_in[6];
    const float* lm_W    = (const float*)d_in[7];
    const float* lm_b    = (const float*)d_in[8];
    float* out = (float*)d_out;

    const long long LOGITS = (long long)BT * Vq;
    int write_logits = (out_size >= LOGITS) ? 1 : 0;
    int do_loss = 1;
    int loss_idx;
    if (write_logits) {
        if ((long long)out_size > LOGITS) loss_idx = (int)LOGITS;
        else { do_loss = 0; loss_idx = 0; }
    } else {
        loss_idx = out_size - 1;
    }

    cudaFuncSetAttribute(mma_kernel, cudaFuncAttributeMaxDynamicSharedMemorySize, SMEM_SZ);

    wprep_kernel<<<(VP2 + 255) / 256, 256>>>(lm_W);
    attn_kernel<<<Bq, 128>>>(idx, tok_emb, pos_emb, Wqp, Wkp, Wvp);
    asplit_kernel<<<BT / 256, 256>>>();
    mma_kernel<<<dim3(NCT, NRT), THR, SMEM_SZ>>>(lm_b, targets, out, write_logits);
    tgt_kernel<<<BT / 256, 256>>>(targets, out, write_logits);
    rowloss_kernel<<<512, 256>>>();
    final_kernel<<<1, 512>>>(out, loss_idx, do_loss);
}